// round 14
// baseline (speedup 1.0000x reference)
#include <cuda_runtime.h>
#include <cstdint>

// Problem constants
#define Bsz   4096
#define CL    8192      // C*L = 8*1024 (GEMM K dim)
#define Hdim  1024
#define Kdim  64
#define Tsteps 32
#define BETA_F 0.9f

// Device scratch (allocation-free rule: use __device__ globals)
__device__ float    g_I1[(size_t)Bsz * Hdim];     // 16 MB
__device__ uint32_t g_P [(size_t)Bsz * Hdim];     // 16 MB spike bit-patterns
__device__ float    g_W2T[(size_t)Hdim * Kdim];   // 256 KB  W2 transposed [h][k]

// ---------------------------------------------------------------------------
// Packed f32x2 helpers (sm_103a). Each lane is IEEE fp32, identical to the
// scalar op: fma lane == fmaf, add lane == __fadd_rn. The two lanes are two
// INDEPENDENT output elements, so per-element reduction order is unchanged.
// ---------------------------------------------------------------------------
__device__ __forceinline__ void fma2(uint64_t& d, uint64_t a, uint64_t b) {
    asm("fma.rn.f32x2 %0, %1, %2, %0;" : "+l"(d) : "l"(a), "l"(b));
}
__device__ __forceinline__ uint64_t add2(uint64_t a, uint64_t b) {
    uint64_t r; asm("add.rn.f32x2 %0, %1, %2;" : "=l"(r) : "l"(a), "l"(b)); return r;
}
__device__ __forceinline__ uint64_t pk2(float lo, float hi) {
    uint64_t r; asm("mov.b64 %0, {%1, %2};" : "=l"(r) : "f"(lo), "f"(hi)); return r;
}
__device__ __forceinline__ void upk2(uint64_t v, float& lo, float& hi) {
    asm("mov.b64 {%0, %1}, %2;" : "=f"(lo), "=f"(hi) : "l"(v));
}

// ---------------------------------------------------------------------------
// Kernel A: fp32 NT GEMM   I1[b][h] = sum_k x[b][k] * W1[h][k]
// BM=128, BN=64, BK=16, TM=8 (as 4 packed M-pairs), TN=4, 256 threads.
//
// NUMERICS (proven in R10, must not change): per output element,
// 4 contiguous chunks of 2048 k-terms, each a SINGLE-accumulator strictly
// ascending-k FMA chain; chunks combined by ascending adds.
// FFMA2 packs two adjacent M-rows per instruction; each lane's chain is
// bit-identical to the scalar version. B is stored DUPLICATED in smem
// ((b,b) pairs) so packed broadcasts come directly from LDS.128.
// ---------------------------------------------------------------------------
__global__ void __launch_bounds__(256) sgemm_nt_chunk2048_f32x2_kernel(
    const float* __restrict__ A,   // [4096][8192]
    const float* __restrict__ Bw)  // [1024][8192]
{
    __shared__ __align__(16) float As[16][132];   // [k][m]
    __shared__ __align__(16) float Bs2[16][136];  // [k][2n] duplicated pairs

    const int tid = threadIdx.x;
    const int tx  = tid & 15;      // n-dir: 16 threads * TN=4 -> 64
    const int ty  = tid >> 4;      // m-dir: 16 threads * TM=8 -> 128
    const int ra  = tid >> 2;      // 0..63 load row
    const int ka  = (tid & 3) << 2;// 0,4,8,12 load k-offset

    const float* Ap = A  + ((size_t)blockIdx.y * 128 + ra) * CL + ka;
    const float* Bp = Bw + ((size_t)blockIdx.x * 64  + ra) * CL + ka;

    float4 a0 = *(const float4*)(Ap);
    float4 a1 = *(const float4*)(Ap + (size_t)64 * CL);
    float4 b0 = *(const float4*)(Bp);

    uint64_t acc2 [4][4];   // [m-pair][n]: inner chunk accumulators
    uint64_t accT2[4][4];   // outer running sums
    #pragma unroll
    for (int i = 0; i < 4; ++i)
        #pragma unroll
        for (int j = 0; j < 4; ++j) { acc2[i][j] = 0ull; accT2[i][j] = 0ull; }

    int tile = 0;
    for (int k0 = 0; k0 < CL; k0 += 16, ++tile) {
        As[ka+0][ra]    = a0.x; As[ka+1][ra]    = a0.y;
        As[ka+2][ra]    = a0.z; As[ka+3][ra]    = a0.w;
        As[ka+0][ra+64] = a1.x; As[ka+1][ra+64] = a1.y;
        As[ka+2][ra+64] = a1.z; As[ka+3][ra+64] = a1.w;
        // duplicated B: columns 2n and 2n+1 both hold b_n
        Bs2[ka+0][2*ra] = b0.x; Bs2[ka+0][2*ra+1] = b0.x;
        Bs2[ka+1][2*ra] = b0.y; Bs2[ka+1][2*ra+1] = b0.y;
        Bs2[ka+2][2*ra] = b0.z; Bs2[ka+2][2*ra+1] = b0.z;
        Bs2[ka+3][2*ra] = b0.w; Bs2[ka+3][2*ra+1] = b0.w;
        __syncthreads();

        if (k0 + 16 < CL) {                 // prefetch next tile
            a0 = *(const float4*)(Ap + k0 + 16);
            a1 = *(const float4*)(Ap + (size_t)64 * CL + k0 + 16);
            b0 = *(const float4*)(Bp + k0 + 16);
        }

        #pragma unroll
        for (int kk = 0; kk < 16; ++kk) {   // strictly ascending k
            // A: 8 m-values = 4 packed pairs, 2x LDS.128
            ulonglong2 apA = *(const ulonglong2*)(&As[kk][ty * 8]);
            ulonglong2 apB = *(const ulonglong2*)(&As[kk][ty * 8 + 4]);
            // B duplicated: (b0,b0,b1,b1),(b2,b2,b3,b3), 2x LDS.128
            ulonglong2 bdA = *(const ulonglong2*)(&Bs2[kk][tx * 8]);
            ulonglong2 bdB = *(const ulonglong2*)(&Bs2[kk][tx * 8 + 4]);
            const uint64_t ap[4] = {apA.x, apA.y, apB.x, apB.y};
            const uint64_t bd[4] = {bdA.x, bdA.y, bdB.x, bdB.y};
            #pragma unroll
            for (int i = 0; i < 4; ++i) {
                fma2(acc2[i][0], ap[i], bd[0]);
                fma2(acc2[i][1], ap[i], bd[1]);
                fma2(acc2[i][2], ap[i], bd[2]);
                fma2(acc2[i][3], ap[i], bd[3]);
            }
        }

        // flush inner chunk every 128 tiles (= 2048 k-terms), ascending adds
        if ((tile & 127) == 127) {
            #pragma unroll
            for (int i = 0; i < 4; ++i)
                #pragma unroll
                for (int j = 0; j < 4; ++j) {
                    accT2[i][j] = add2(accT2[i][j], acc2[i][j]);
                    acc2[i][j] = 0ull;
                }
        }
        __syncthreads();
    }

    // store: pair lane0 -> row ty*8+2i, lane1 -> row ty*8+2i+1
    float* Cp = g_I1 + ((size_t)blockIdx.y * 128 + ty * 8) * Hdim
                     + blockIdx.x * 64 + tx * 4;
    #pragma unroll
    for (int i = 0; i < 4; ++i) {
        float r0[4], r1[4];
        #pragma unroll
        for (int j = 0; j < 4; ++j) upk2(accT2[i][j], r0[j], r1[j]);
        *(float4*)(Cp + (size_t)(2*i)   * Hdim) = make_float4(r0[0], r0[1], r0[2], r0[3]);
        *(float4*)(Cp + (size_t)(2*i+1) * Hdim) = make_float4(r1[0], r1[1], r1[2], r1[3]);
    }
}

// ---------------------------------------------------------------------------
// Kernel B: per-(b,h) LIF layer-1 recurrence -> 32-bit spike pattern.
// Non-contracted mul+add (flip-neutral, matches XLA elementwise).
// ---------------------------------------------------------------------------
__global__ void spike_kernel()
{
    const size_t i = (size_t)blockIdx.x * blockDim.x + threadIdx.x;
    const float I = g_I1[i];
    float v = 0.f;
    uint32_t p = 0u;
    #pragma unroll
    for (int t = 0; t < Tsteps; ++t) {
        v = __fadd_rn(__fmul_rn(BETA_F, v), I);
        if (__fsub_rn(v, 1.0f) >= 0.0f) { p |= (1u << t); v = __fsub_rn(v, 1.0f); }
    }
    g_P[i] = p;
}

// ---------------------------------------------------------------------------
// Kernel T: transpose W2[k][h] -> g_W2T[h][k] (coalesced layer-2 reads)
// ---------------------------------------------------------------------------
__global__ void w2t_kernel(const float* __restrict__ W2)
{
    const int i = blockIdx.x * blockDim.x + threadIdx.x; // over Kdim*Hdim
    const int k = i >> 10;       // /Hdim
    const int h = i & 1023;      // %Hdim
    g_W2T[h * Kdim + k] = W2[i];
}

// ---------------------------------------------------------------------------
// Kernel C: layer-2.  Block = 4 batch rows; 256 threads.
// Phase 1: thread = (bl, k-pair, t-half). 16 timesteps x 2 k-columns per
// thread, packed add.rn.f32x2 (spike mask is identical for both k lanes).
// Accumulation: chunk-32 inner + plain outer adds, ascending h — within the
// proven flip-free tolerance class (R3==R7: layer-2 delta up to ~1e-6 causes
// zero output flips). Silent-pattern skip remains an exact no-op.
// Phase 2: thread = (bl, k) runs the 32-step v2/count recurrence from smem.
// ---------------------------------------------------------------------------
__global__ void __launch_bounds__(256) layer2_kernel(float* __restrict__ out)
{
    __shared__ uint32_t sP[4][Hdim];        // 16 KB
    __shared__ float    sc[4][Tsteps][65];  // [bl][t][k], pad 65: 33.3 KB

    const int tid   = threadIdx.x;
    const int kp    = tid & 31;         // k-pair index: k = 2*kp, 2*kp+1
    const int thalf = (tid >> 5) & 1;   // 0: t 0-15, 1: t 16-31
    const int bl    = tid >> 6;         // local batch 0..3
    const int b0    = blockIdx.x * 4;
    const int t0    = thalf * 16;

    for (int i = tid; i < 4 * Hdim; i += 256)
        sP[i >> 10][i & 1023] = g_P[(size_t)(b0 + (i >> 10)) * Hdim + (i & 1023)];
    __syncthreads();

    uint64_t c2[16];
    #pragma unroll
    for (int t = 0; t < 16; ++t) c2[t] = 0ull;

    for (int hb = 0; hb < Hdim; hb += 32) {
        uint64_t inner2[16];
        #pragma unroll
        for (int t = 0; t < 16; ++t) inner2[t] = 0ull;

        #pragma unroll 4
        for (int h = hb; h < hb + 32; ++h) {
            const uint32_t bits = (sP[bl][h] >> t0) & 0xFFFFu;  // warp-uniform
            if (bits) {
                const float2 w = *(const float2*)(&g_W2T[h * Kdim + 2 * kp]);
                const uint64_t w2 = pk2(w.x, w.y);
                #pragma unroll
                for (int t = 0; t < 16; ++t)
                    if (bits & (1u << t)) inner2[t] = add2(inner2[t], w2);
            }
        }
        #pragma unroll
        for (int t = 0; t < 16; ++t) c2[t] = add2(c2[t], inner2[t]);
    }

    // stage c[t] to smem for the recurrence phase
    #pragma unroll
    for (int t = 0; t < 16; ++t) {
        float lo, hi;
        upk2(c2[t], lo, hi);
        sc[bl][t0 + t][2 * kp]     = lo;
        sc[bl][t0 + t][2 * kp + 1] = hi;
    }
    __syncthreads();

    // Phase 2: v2 recurrence + spike count (mul+add, no fma)
    const int k   = tid & 63;
    const int bl2 = tid >> 6;
    float v2 = 0.f, cnt = 0.f;
    #pragma unroll
    for (int t = 0; t < Tsteps; ++t) {
        v2 = __fadd_rn(__fmul_rn(BETA_F, v2), sc[bl2][t][k]);
        if (__fsub_rn(v2, 1.0f) >= 0.0f) { v2 = __fsub_rn(v2, 1.0f); cnt += 1.0f; }
    }
    out[(size_t)(b0 + bl2) * Kdim + k] = cnt;
}

// ---------------------------------------------------------------------------
extern "C" void kernel_launch(void* const* d_in, const int* in_sizes, int n_in,
                              void* d_out, int out_size)
{
    const float* x  = (const float*)d_in[0];   // (4096, 8, 1024) == (4096, 8192)
    const float* W1 = (const float*)d_in[1];   // (1024, 8192)
    const float* W2 = (const float*)d_in[2];   // (64, 1024)
    float* out = (float*)d_out;                // (4096, 64)

    // W2 transpose (independent of GEMM, tiny)
    w2t_kernel<<<(Kdim * Hdim) / 256, 256>>>(W2);

    // I1 = x @ W1^T  (chunk-2048 ascending FMA via packed FFMA2)
    dim3 grid(Hdim / 64, Bsz / 128);
    sgemm_nt_chunk2048_f32x2_kernel<<<grid, 256>>>(x, W1);

    // spike trains
    spike_kernel<<<(Bsz * Hdim) / 256, 256>>>();

    // layer 2 + counts
    layer2_kernel<<<Bsz / 4, 256>>>(out);
}

// round 17
// speedup vs baseline: 1.7329x; 1.7329x over previous
#include <cuda_runtime.h>
#include <cstdint>

// Problem constants
#define Bsz   4096
#define CL    8192      // C*L = 8*1024 (GEMM K dim)
#define Hdim  1024
#define Kdim  64
#define Tsteps 32
#define BETA_F 0.9f

// Device scratch (allocation-free rule: use __device__ globals)
__device__ uint32_t g_P [(size_t)Bsz * Hdim];     // 16 MB spike bit-patterns
__device__ float    g_W2T[(size_t)Hdim * Kdim];   // 256 KB  W2 transposed [h][k]

// ---------------------------------------------------------------------------
// Packed f32x2 helpers (sm_103a) — used ONLY in layer2 (proven faster there;
// proven SLOWER in the GEMM fma path, R14).
// ---------------------------------------------------------------------------
__device__ __forceinline__ uint64_t add2(uint64_t a, uint64_t b) {
    uint64_t r; asm("add.rn.f32x2 %0, %1, %2;" : "=l"(r) : "l"(a), "l"(b)); return r;
}
__device__ __forceinline__ uint64_t pk2(float lo, float hi) {
    uint64_t r; asm("mov.b64 %0, {%1, %2};" : "=l"(r) : "f"(lo), "f"(hi)); return r;
}
__device__ __forceinline__ void upk2(uint64_t v, float& lo, float& hi) {
    asm("mov.b64 {%0, %1}, %2;" : "=f"(lo), "=f"(hi) : "l"(v));
}

// ---------------------------------------------------------------------------
// Spike recurrence (layer-1 LIF): I constant per element -> 32-bit pattern.
// Non-contracted mul+add (proven flip-neutral; matches XLA elementwise).
// ---------------------------------------------------------------------------
__device__ __forceinline__ uint32_t spike_train(float I) {
    float v = 0.f;
    uint32_t p = 0u;
    #pragma unroll
    for (int t = 0; t < Tsteps; ++t) {
        v = __fadd_rn(__fmul_rn(BETA_F, v), I);
        if (__fsub_rn(v, 1.0f) >= 0.0f) { p |= (1u << t); v = __fsub_rn(v, 1.0f); }
    }
    return p;
}

// ---------------------------------------------------------------------------
// Kernel A: fp32 NT GEMM + fused spike epilogue.
// I1[b][h] = sum_k x[b][k] * W1[h][k];  g_P[b][h] = spike_train(I1[b][h]).
// BM=128, BN=64, BK=16, TM=8, TN=4, 256 threads — the R10-proven kernel
// (scalar FFMA; R14 showed the f32x2 fma path is ~1.9x slower here).
//
// NUMERICS (R10-proven contract, must not change): per output element,
// 4 contiguous chunks of 2048 k-terms, each a SINGLE-accumulator strictly
// ascending-k FMA chain; chunks combined by ascending adds.
// ---------------------------------------------------------------------------
__global__ void __launch_bounds__(256) sgemm_spike_kernel(
    const float* __restrict__ A,   // [4096][8192]
    const float* __restrict__ Bw)  // [1024][8192]
{
    __shared__ __align__(16) float As[16][132];  // [k][m]
    __shared__ __align__(16) float Bs[16][68];   // [k][n]

    const int tid = threadIdx.x;
    const int tx  = tid & 15;      // n-dir: 16 threads * TN=4 -> 64
    const int ty  = tid >> 4;      // m-dir: 16 threads * TM=8 -> 128
    const int ra  = tid >> 2;      // 0..63 load row
    const int ka  = (tid & 3) << 2;// 0,4,8,12 load k-offset

    const float* Ap = A  + ((size_t)blockIdx.y * 128 + ra) * CL + ka;
    const float* Bp = Bw + ((size_t)blockIdx.x * 64  + ra) * CL + ka;

    float4 a0 = *(const float4*)(Ap);
    float4 a1 = *(const float4*)(Ap + (size_t)64 * CL);
    float4 b0 = *(const float4*)(Bp);

    float acc[8][4];    // inner chunk accumulator (ascending FMA, 2048 terms)
    float accT[8][4];   // outer running sum (ascending adds across chunks)
    #pragma unroll
    for (int i = 0; i < 8; ++i)
        #pragma unroll
        for (int j = 0; j < 4; ++j) { acc[i][j] = 0.f; accT[i][j] = 0.f; }

    int tile = 0;
    for (int k0 = 0; k0 < CL; k0 += 16, ++tile) {
        As[ka+0][ra]    = a0.x; As[ka+1][ra]    = a0.y;
        As[ka+2][ra]    = a0.z; As[ka+3][ra]    = a0.w;
        As[ka+0][ra+64] = a1.x; As[ka+1][ra+64] = a1.y;
        As[ka+2][ra+64] = a1.z; As[ka+3][ra+64] = a1.w;
        Bs[ka+0][ra]    = b0.x; Bs[ka+1][ra]    = b0.y;
        Bs[ka+2][ra]    = b0.z; Bs[ka+3][ra]    = b0.w;
        __syncthreads();

        if (k0 + 16 < CL) {                 // prefetch next tile
            a0 = *(const float4*)(Ap + k0 + 16);
            a1 = *(const float4*)(Ap + (size_t)64 * CL + k0 + 16);
            b0 = *(const float4*)(Bp + k0 + 16);
        }

        #pragma unroll
        for (int kk = 0; kk < 16; ++kk) {   // strictly ascending k
            float4 av0 = *(const float4*)(&As[kk][ty * 8]);
            float4 av1 = *(const float4*)(&As[kk][ty * 8 + 4]);
            float4 bv  = *(const float4*)(&Bs[kk][tx * 4]);
            float ar[8] = {av0.x, av0.y, av0.z, av0.w,
                           av1.x, av1.y, av1.z, av1.w};
            float br[4] = {bv.x, bv.y, bv.z, bv.w};
            #pragma unroll
            for (int i = 0; i < 8; ++i)
                #pragma unroll
                for (int j = 0; j < 4; ++j)
                    acc[i][j] = fmaf(ar[i], br[j], acc[i][j]);
        }

        // flush inner chunk every 128 tiles (= 2048 k-terms), ascending adds
        if ((tile & 127) == 127) {
            #pragma unroll
            for (int i = 0; i < 8; ++i)
                #pragma unroll
                for (int j = 0; j < 4; ++j) {
                    accT[i][j] = __fadd_rn(accT[i][j], acc[i][j]);
                    acc[i][j] = 0.f;
                }
        }
        __syncthreads();
    }

    // Fused spike epilogue: pattern per element, store packed uint4.
    uint32_t* Pp = g_P + ((size_t)blockIdx.y * 128 + ty * 8) * Hdim
                       + blockIdx.x * 64 + tx * 4;
    #pragma unroll
    for (int i = 0; i < 8; ++i) {
        uint4 pv;
        pv.x = spike_train(accT[i][0]);
        pv.y = spike_train(accT[i][1]);
        pv.z = spike_train(accT[i][2]);
        pv.w = spike_train(accT[i][3]);
        *(uint4*)(Pp + (size_t)i * Hdim) = pv;
    }
}

// ---------------------------------------------------------------------------
// Kernel T: transpose W2[k][h] -> g_W2T[h][k] (coalesced layer-2 reads)
// ---------------------------------------------------------------------------
__global__ void w2t_kernel(const float* __restrict__ W2)
{
    const int i = blockIdx.x * blockDim.x + threadIdx.x; // over Kdim*Hdim
    const int k = i >> 10;       // /Hdim
    const int h = i & 1023;      // %Hdim
    g_W2T[h * Kdim + k] = W2[i];
}

// ---------------------------------------------------------------------------
// Kernel C: layer-2 (R14-proven: 455 us, rel_err bit-identical).
// Block = 4 batch rows; 256 threads.
// Phase 1: thread = (bl, k-pair, t-half): 16 t x 2 k, packed add.rn.f32x2.
// Accumulation: chunk-32 inner + plain outer adds, ascending h — inside the
// proven flip-free tolerance class. Silent-pattern skip is an exact no-op.
// Phase 2: thread = (bl, k) runs the 32-step v2/count recurrence from smem.
// ---------------------------------------------------------------------------
__global__ void __launch_bounds__(256) layer2_kernel(float* __restrict__ out)
{
    __shared__ uint32_t sP[4][Hdim];        // 16 KB
    __shared__ float    sc[4][Tsteps][65];  // [bl][t][k], pad 65

    const int tid   = threadIdx.x;
    const int kp    = tid & 31;         // k-pair index: k = 2*kp, 2*kp+1
    const int thalf = (tid >> 5) & 1;   // 0: t 0-15, 1: t 16-31
    const int bl    = tid >> 6;         // local batch 0..3
    const int b0    = blockIdx.x * 4;
    const int t0    = thalf * 16;

    for (int i = tid; i < 4 * Hdim; i += 256)
        sP[i >> 10][i & 1023] = g_P[(size_t)(b0 + (i >> 10)) * Hdim + (i & 1023)];
    __syncthreads();

    uint64_t c2[16];
    #pragma unroll
    for (int t = 0; t < 16; ++t) c2[t] = 0ull;

    for (int hb = 0; hb < Hdim; hb += 32) {
        uint64_t inner2[16];
        #pragma unroll
        for (int t = 0; t < 16; ++t) inner2[t] = 0ull;

        #pragma unroll 4
        for (int h = hb; h < hb + 32; ++h) {
            const uint32_t bits = (sP[bl][h] >> t0) & 0xFFFFu;  // warp-uniform
            if (bits) {
                const float2 w = *(const float2*)(&g_W2T[h * Kdim + 2 * kp]);
                const uint64_t w2 = pk2(w.x, w.y);
                #pragma unroll
                for (int t = 0; t < 16; ++t)
                    if (bits & (1u << t)) inner2[t] = add2(inner2[t], w2);
            }
        }
        #pragma unroll
        for (int t = 0; t < 16; ++t) c2[t] = add2(c2[t], inner2[t]);
    }

    // stage c[t] to smem for the recurrence phase
    #pragma unroll
    for (int t = 0; t < 16; ++t) {
        float lo, hi;
        upk2(c2[t], lo, hi);
        sc[bl][t0 + t][2 * kp]     = lo;
        sc[bl][t0 + t][2 * kp + 1] = hi;
    }
    __syncthreads();

    // Phase 2: v2 recurrence + spike count (mul+add, no fma)
    const int k   = tid & 63;
    const int bl2 = tid >> 6;
    float v2 = 0.f, cnt = 0.f;
    #pragma unroll
    for (int t = 0; t < Tsteps; ++t) {
        v2 = __fadd_rn(__fmul_rn(BETA_F, v2), sc[bl2][t][k]);
        if (__fsub_rn(v2, 1.0f) >= 0.0f) { v2 = __fsub_rn(v2, 1.0f); cnt += 1.0f; }
    }
    out[(size_t)(b0 + bl2) * Kdim + k] = cnt;
}

// ---------------------------------------------------------------------------
extern "C" void kernel_launch(void* const* d_in, const int* in_sizes, int n_in,
                              void* d_out, int out_size)
{
    const float* x  = (const float*)d_in[0];   // (4096, 8, 1024) == (4096, 8192)
    const float* W1 = (const float*)d_in[1];   // (1024, 8192)
    const float* W2 = (const float*)d_in[2];   // (64, 1024)
    float* out = (float*)d_out;                // (4096, 64)

    // W2 transpose (independent of GEMM, tiny)
    w2t_kernel<<<(Kdim * Hdim) / 256, 256>>>(W2);

    // I1 = x @ W1^T (chunk-2048 ascending FMA) + fused spike trains
    dim3 grid(Hdim / 64, Bsz / 128);
    sgemm_spike_kernel<<<grid, 256>>>(x, W1);

    // layer 2 + counts
    layer2_kernel<<<Bsz / 4, 256>>>(out);
}